// round 2
// baseline (speedup 1.0000x reference)
#include <cuda_runtime.h>
#include <math.h>

#define S  20
#define SS 400

// ---- device scratch (allocation-free rule: __device__ globals) ----
__device__ float g_Q[64 * SS];        // per (m,k): Q col-major, col t contiguous
__device__ float g_an[64];            // per (m,k): inf-norm of Q
__device__ float g_tauv[65536];       // per (m,rate): softplus(tau_kernel)
__device__ float g_P[4096 * SS];      // per (m,b,k): P row-major

__device__ __forceinline__ float softplusf(float x) {
    return fmaxf(x, 0.0f) + log1pf(expf(-fabsf(x)));
}
__device__ __forceinline__ float wred_max(float v) {
#pragma unroll
    for (int o = 16; o > 0; o >>= 1) v = fmaxf(v, __shfl_xor_sync(0xffffffffu, v, o));
    return v;
}
__device__ __forceinline__ float wred_sum(float v) {
#pragma unroll
    for (int o = 16; o > 0; o >>= 1) v += __shfl_xor_sync(0xffffffffu, v, o);
    return v;
}

// ---------------- kernel 0: build Q (per m,k) + tau table ----------------
// blocks [0, m*k): Q build (first warp only). blocks [m*k, m*k+tb): tau table.
__global__ void setup_kernel(const float* __restrict__ tauk,
                             const float* __restrict__ exch,
                             const float* __restrict__ eq,
                             int mk, int mnr)
{
    __shared__ float sp[S];
    if ((int)blockIdx.x < mk) {
        if (threadIdx.x >= 32) return;
        const int lane = threadIdx.x;
        const int mat  = blockIdx.x;
        const float* Ek = exch + (size_t)mat * SS;
        const float* ek = eq   + (size_t)mat * S;

        // softmax p
        float x  = (lane < S) ? ek[lane] : -3.0e38f;
        float mx = wred_max(x);
        float ex = (lane < S) ? expf(x - mx) : 0.0f;
        float sm = wred_sum(ex);
        float pl = ex / sm;
        if (lane < S) sp[lane] = pl;
        __syncwarp();

        float qrow[S];
        float diag = 0.0f;
        if (lane < S) {
#pragma unroll
            for (int j = 0; j < S; j++) {
                float r = (j == lane) ? 0.0f
                        : softplusf(0.5f * (Ek[lane * S + j] + Ek[j * S + lane]));
                float q = r * sp[j];
                qrow[j] = q;
                diag += q;
            }
            qrow[lane] = -diag;
        }
        float mue = wred_sum((lane < S) ? pl * diag : 0.0f);
        float inv = 1.0f / fmaxf(mue, 1e-16f);
        if (lane < S) {
#pragma unroll
            for (int j = 0; j < S; j++) g_Q[mat * SS + j * S + lane] = qrow[j] * inv;
        }
        float an = wred_max((lane < S) ? 2.0f * diag * inv : 0.0f);
        if (lane == 0) g_an[mat] = an;
    } else {
        const int base = ((int)blockIdx.x - mk) * blockDim.x + threadIdx.x;
        if (base < mnr) g_tauv[base] = softplusf(tauk[base]);
    }
}

// ---------------- kernel A: batched expm, one warp per (m,b,k) ----------------
#define WPB 8
__global__ void __launch_bounds__(32 * WPB)
expm_kernel(const int* __restrict__ ridx, int b, int k, int nr, int total)
{
    __shared__ __align__(16) float sM[WPB][SS];

    const int wid  = threadIdx.x >> 5;
    const int lane = threadIdx.x & 31;
    const int gid  = blockIdx.x * WPB + wid;
    if (gid >= total) return;

    const int kk  = gid % k;
    const int bb  = gid / k;          // = mi*b + bi
    const int mi  = bb / b;
    const int mat = mi * k + kk;

    // copy Q (col-major) into this warp's smem slot
    float4*       dst4 = reinterpret_cast<float4*>(&sM[wid][0]);
    const float4* src4 = reinterpret_cast<const float4*>(&g_Q[mat * SS]);
#pragma unroll
    for (int i = 0; i < 4; i++) {
        int idx = lane + 32 * i;
        if (idx < 100) dst4[idx] = src4[idx];
    }

    const float tau = g_tauv[mi * nr + ridx[bb]];
    float nrm = tau * g_an[mat];
    int sc = 0;
    while (nrm > 1.0f && sc < 40) { nrm *= 0.5f; sc++; }
    const float factor = ldexpf(tau, -sc);
    __syncwarp();

    const float4* Qc4 = reinterpret_cast<const float4*>(&sM[wid][0]);
    const int col = (lane < S) ? lane : 0;

    // T1 = factor*Q[:,col];  E = I + T1
    float t[S], e[S];
#pragma unroll
    for (int i = 0; i < S; i++) {
        t[i] = factor * sM[wid][col * S + i];
        e[i] = t[i] + ((i == lane) ? 1.0f : 0.0f);
    }

    // Taylor terms j = 2..J with theta = 1.0
    const int J = 10;
#pragma unroll 1
    for (int j = 2; j <= J; j++) {
        const float coef = factor / (float)j;
        float c[S];
#pragma unroll
        for (int i = 0; i < S; i++) c[i] = 0.0f;
#pragma unroll
        for (int tt = 0; tt < S; tt++) {
            const float tv = t[tt];
#pragma unroll
            for (int q = 0; q < 5; q++) {
                float4 v = Qc4[tt * 5 + q];
                c[4 * q + 0] = fmaf(v.x, tv, c[4 * q + 0]);
                c[4 * q + 1] = fmaf(v.y, tv, c[4 * q + 1]);
                c[4 * q + 2] = fmaf(v.z, tv, c[4 * q + 2]);
                c[4 * q + 3] = fmaf(v.w, tv, c[4 * q + 3]);
            }
        }
#pragma unroll
        for (int i = 0; i < S; i++) { t[i] = c[i] * coef; e[i] += t[i]; }
    }

    // squarings
#pragma unroll 1
    for (int r = 0; r < sc; r++) {
        __syncwarp();
        if (lane < S) {
#pragma unroll
            for (int i = 0; i < S; i++) sM[wid][lane * S + i] = e[i];  // col-major
        }
        __syncwarp();
        float c[S];
#pragma unroll
        for (int i = 0; i < S; i++) c[i] = 0.0f;
#pragma unroll
        for (int tt = 0; tt < S; tt++) {
            const float tv = e[tt];
#pragma unroll
            for (int q = 0; q < 5; q++) {
                float4 v = Qc4[tt * 5 + q];
                c[4 * q + 0] = fmaf(v.x, tv, c[4 * q + 0]);
                c[4 * q + 1] = fmaf(v.y, tv, c[4 * q + 1]);
                c[4 * q + 2] = fmaf(v.z, tv, c[4 * q + 2]);
                c[4 * q + 3] = fmaf(v.w, tv, c[4 * q + 3]);
            }
        }
#pragma unroll
        for (int i = 0; i < S; i++) e[i] = c[i];
    }

    // store P row-major: P[i][lane] = e[i]
    if (lane < S) {
        float* P = &g_P[(size_t)gid * SS];
#pragma unroll
        for (int i = 0; i < S; i++) P[i * S + lane] = e[i];
    }
}

// ---------------- kernel B: gather/stream, one block per (m,b) ----------------
template <int K>
__global__ void __launch_bounds__(256)
gather_kernel(const int* __restrict__ seq, float* __restrict__ out, int L)
{
    __shared__ __align__(16) float sP[K * SS];
    __shared__ int sseq[1024];

    const int bid = blockIdx.x;     // (m,b) flat; matches expm gid/k ordering
    const int tid = threadIdx.x;

    // stage P matrices (contiguous in g_P) and the sequence row
    const float4* src4 = reinterpret_cast<const float4*>(&g_P[(size_t)bid * K * SS]);
    float4*       dst4 = reinterpret_cast<float4*>(sP);
#pragma unroll
    for (int i = tid; i < K * 100; i += 256) dst4[i] = src4[i];
    for (int i = tid; i < L; i += 256) sseq[i] = seq[(size_t)bid * L + i];
    __syncthreads();

    const float4* sP4 = reinterpret_cast<const float4*>(sP);
    const int nf4 = L * K * 5;
    float4* out4 = reinterpret_cast<float4*>(out) + (size_t)bid * nf4;

    for (int g = tid; g < nf4; g += 256) {
        const int l  = g / (K * 5);
        const int j  = g - l * (K * 5);
        const int kq = j / 5;
        const int s4 = j - kq * 5;
        const float4 v = sP4[kq * 100 + sseq[l] * 5 + s4];
        __stcs(&out4[g], v);
    }
}

extern "C" void kernel_launch(void* const* d_in, const int* in_sizes, int n_in,
                              void* d_out, int out_size)
{
    const int*   seq  = (const int*)  d_in[0];
    const int*   ridx = (const int*)  d_in[1];
    const float* tauk = (const float*)d_in[2];
    const float* exch = (const float*)d_in[3];
    const float* eq   = (const float*)d_in[4];
    float*       out  = (float*)d_out;

    const int n_seq = in_sizes[0];
    const int n_ri  = in_sizes[1];
    const int n_tau = in_sizes[2];
    const int n_eq  = in_sizes[4];

    const int mk = n_eq / S;
    const int k  = out_size / (n_seq * S);
    const int m  = mk / k;
    const int b  = n_ri / m;
    const int L  = n_seq / n_ri;
    const int nr = n_tau / m;
    const int mnr = m * nr;
    const int total = m * b * k;

    // kernel 0: Q build + tau table
    const int tb = (mnr + 255) / 256;
    setup_kernel<<<mk + tb, 256>>>(tauk, exch, eq, mk, mnr);

    // kernel A: expm
    expm_kernel<<<(total + WPB - 1) / WPB, 32 * WPB>>>(ridx, b, k, nr, total);

    // kernel B: gather
    switch (k) {
        case 1: gather_kernel<1><<<m * b, 256>>>(seq, out, L); break;
        case 2: gather_kernel<2><<<m * b, 256>>>(seq, out, L); break;
        case 3: gather_kernel<3><<<m * b, 256>>>(seq, out, L); break;
        case 4: gather_kernel<4><<<m * b, 256>>>(seq, out, L); break;
        default: break;
    }
}

// round 3
// speedup vs baseline: 1.1529x; 1.1529x over previous
#include <cuda_runtime.h>
#include <math.h>

#define S  20
#define SS 400

__device__ __forceinline__ float softplusf(float x) {
    return fmaxf(x, 0.0f) + log1pf(expf(-fabsf(x)));
}
__device__ __forceinline__ float wred_max(float v) {
#pragma unroll
    for (int o = 16; o > 0; o >>= 1) v = fmaxf(v, __shfl_xor_sync(0xffffffffu, v, o));
    return v;
}
__device__ __forceinline__ float wred_sum(float v) {
#pragma unroll
    for (int o = 16; o > 0; o >>= 1) v += __shfl_xor_sync(0xffffffffu, v, o);
    return v;
}

// Fused kernel. BPB (m,b)-pairs per block, one warp per (pair, k) matrix.
// expm via scaling-and-squaring + Horner-form Taylor (register working set = 2 cols).
// Shared: sM[WARPS][400] (Q / E col-major scratch), sP[WARPS][400] (final P row-major).
template <int K, int BPB>
__global__ void __launch_bounds__(32 * K * BPB, 3)
fused_kernel(const int*   __restrict__ seq,    // (m,b,L)
             const int*   __restrict__ ridx,   // (m,b)
             const float* __restrict__ tauk,   // (m,num_rates)
             const float* __restrict__ exch,   // (m,K,20,20)
             const float* __restrict__ eq,     // (m,K,20)
             float*       __restrict__ out,    // (m,b,L,K,20)
             int mb, int b, int L, int nr)
{
    constexpr int WARPS = K * BPB;
    extern __shared__ float smem[];
    float* sM = smem;                  // [WARPS][SS] col-major workspace
    float* sP = smem + WARPS * SS;     // [WARPS][SS] = [BPB][K][SS] row-major P

    const int tid  = threadIdx.x;
    const int wid  = tid >> 5;
    const int lane = tid & 31;
    const int pair = wid / K;
    const int kk   = wid - pair * K;
    const int pb   = blockIdx.x * BPB + pair;   // flattened (m,b)

    if (pb < mb) {
        const int mi = pb / b;
        const float* Ek = exch + (size_t)(mi * K + kk) * SS;
        const float* ek = eq   + (size_t)(mi * K + kk) * S;
        float* Qs = sM + wid * SS;     // col-major Q: Q[i][t] at [t*S+i]
        float* Ps = sP + wid * SS;     // scratch now, P later

        // ---- softmax p (broadcast via shared scratch) ----
        float x  = (lane < S) ? ek[lane] : -3.0e38f;
        float mx = wred_max(x);
        float ex = (lane < S) ? expf(x - mx) : 0.0f;
        float sm = wred_sum(ex);
        float pl = ex / sm;
        if (lane < S) Ps[lane] = pl;
        __syncwarp();

        // ---- Q row (lane) ----
        float diag = 0.0f;
        if (lane < S) {
            float qrow[S];
#pragma unroll
            for (int j = 0; j < S; j++) {
                float r = (j == lane) ? 0.0f
                        : softplusf(0.5f * (Ek[lane * S + j] + Ek[j * S + lane]));
                float q = r * Ps[j];
                qrow[j] = q;
                diag += q;
            }
            qrow[lane] = -diag;
            float mue = 0.0f;  // computed below via wred over all lanes
            (void)mue;
            // stash row temporarily in registers; need mue first
            float contrib = pl * diag;
            float mtot = contrib;
#pragma unroll
            for (int o = 16; o > 0; o >>= 1) mtot += __shfl_xor_sync(0xffffffffu, mtot, o);
            float inv = 1.0f / fmaxf(mtot, 1e-16f);
#pragma unroll
            for (int j = 0; j < S; j++) Qs[j * S + lane] = qrow[j] * inv;
            diag *= inv;
        } else {
            // lanes >= S must still participate in the shuffle reduction
            float mtot = 0.0f;
#pragma unroll
            for (int o = 16; o > 0; o >>= 1) mtot += __shfl_xor_sync(0xffffffffu, mtot, o);
        }
        float an = wred_max((lane < S) ? 2.0f * diag : 0.0f);  // inf-norm of normalized Q

        // ---- tau, scaling ----
        const float tau = softplusf(tauk[mi * nr + ridx[pb]]);
        float nrm = tau * an;
        int sc = 0;
        while (nrm > 0.5f && sc < 40) { nrm *= 0.5f; sc++; }
        const float factor = ldexpf(tau, -sc);
        __syncwarp();

        const float4* Q4 = reinterpret_cast<const float4*>(Qs);
        const int col = (lane < S) ? lane : 0;

        // ---- Horner Taylor: A = I + f/J*Q, then A <- I + (f/j) Q A, j=J-1..1 ----
        const int J = 9;
        float a[S];
#pragma unroll
        for (int i = 0; i < S; i++)
            a[i] = (factor / (float)J) * Qs[col * S + i] + ((i == lane) ? 1.0f : 0.0f);

#pragma unroll 1
        for (int j = J - 1; j >= 1; j--) {
            const float coef = factor / (float)j;
            float c[S];
#pragma unroll
            for (int i = 0; i < S; i++) c[i] = 0.0f;
#pragma unroll
            for (int t = 0; t < S; t++) {
                const float av = a[t];
#pragma unroll
                for (int q = 0; q < 5; q++) {
                    float4 v = Q4[t * 5 + q];
                    c[4*q+0] = fmaf(v.x, av, c[4*q+0]);
                    c[4*q+1] = fmaf(v.y, av, c[4*q+1]);
                    c[4*q+2] = fmaf(v.z, av, c[4*q+2]);
                    c[4*q+3] = fmaf(v.w, av, c[4*q+3]);
                }
            }
#pragma unroll
            for (int i = 0; i < S; i++) a[i] = coef * c[i] + ((i == lane) ? 1.0f : 0.0f);
        }

        // ---- squarings ----
#pragma unroll 1
        for (int r = 0; r < sc; r++) {
            __syncwarp();
            if (lane < S) {
#pragma unroll
                for (int i = 0; i < S; i++) Qs[lane * S + i] = a[i];  // E col-major
            }
            __syncwarp();
            float c[S];
#pragma unroll
            for (int i = 0; i < S; i++) c[i] = 0.0f;
#pragma unroll
            for (int t = 0; t < S; t++) {
                const float av = a[t];
#pragma unroll
                for (int q = 0; q < 5; q++) {
                    float4 v = Q4[t * 5 + q];
                    c[4*q+0] = fmaf(v.x, av, c[4*q+0]);
                    c[4*q+1] = fmaf(v.y, av, c[4*q+1]);
                    c[4*q+2] = fmaf(v.z, av, c[4*q+2]);
                    c[4*q+3] = fmaf(v.w, av, c[4*q+3]);
                }
            }
#pragma unroll
            for (int i = 0; i < S; i++) a[i] = c[i];
        }

        // ---- P row-major: P[i][col] = a[i] ----
        __syncwarp();
        if (lane < S) {
#pragma unroll
            for (int i = 0; i < S; i++) Ps[i * S + col] = a[i];
        }
    }
    __syncthreads();

    // ---------------- gather: out[pb,l,k,:] = P[pb,k][seq[pb,l],:] ----------------
    const int nf4 = L * K * 5;
#pragma unroll
    for (int p = 0; p < BPB; p++) {
        const int pbg = blockIdx.x * BPB + p;
        if (pbg >= mb) break;
        const int*    sq   = seq + (size_t)pbg * L;
        float4*       out4 = reinterpret_cast<float4*>(out) + (size_t)pbg * nf4;
        const float4* P4   = reinterpret_cast<const float4*>(sP + p * K * SS);  // [K][100]

        for (int g = tid; g < nf4; g += 32 * K * BPB) {
            const int l  = g / (K * 5);
            const int j  = g - l * (K * 5);
            const int kq = j / 5;
            const int s4 = j - kq * 5;
            const int s0 = __ldg(sq + l);
            __stcs(&out4[g], P4[kq * 100 + s0 * 5 + s4]);
        }
    }
}

template <int K, int BPB>
static void launch(const int* seq, const int* ridx, const float* tauk,
                   const float* exch, const float* eq, float* out,
                   int mb, int b, int L, int nr)
{
    const int grid = (mb + BPB - 1) / BPB;
    const int smem = 2 * K * BPB * SS * (int)sizeof(float);
    fused_kernel<K, BPB><<<grid, 32 * K * BPB, smem>>>(seq, ridx, tauk, exch, eq, out, mb, b, L, nr);
}

extern "C" void kernel_launch(void* const* d_in, const int* in_sizes, int n_in,
                              void* d_out, int out_size)
{
    const int*   seq  = (const int*)  d_in[0];
    const int*   ridx = (const int*)  d_in[1];
    const float* tauk = (const float*)d_in[2];
    const float* exch = (const float*)d_in[3];
    const float* eq   = (const float*)d_in[4];
    float*       out  = (float*)d_out;

    const int n_seq = in_sizes[0];
    const int n_ri  = in_sizes[1];
    const int n_tau = in_sizes[2];
    const int n_eq  = in_sizes[4];

    const int mk = n_eq / S;
    const int k  = out_size / (n_seq * S);
    const int m  = mk / k;
    const int b  = n_ri / m;
    const int L  = n_seq / n_ri;
    const int nr = n_tau / m;
    const int mb = m * b;

    switch (k) {
        case 1: launch<1, 8>(seq, ridx, tauk, exch, eq, out, mb, b, L, nr); break;
        case 2: launch<2, 4>(seq, ridx, tauk, exch, eq, out, mb, b, L, nr); break;
        case 3: launch<3, 2>(seq, ridx, tauk, exch, eq, out, mb, b, L, nr); break;
        case 4: launch<4, 2>(seq, ridx, tauk, exch, eq, out, mb, b, L, nr); break;
        default: break;
    }
}

// round 4
// speedup vs baseline: 1.1705x; 1.0153x over previous
#include <cuda_runtime.h>
#include <math.h>

#define S  20
#define SS 400

__device__ __forceinline__ float softplusf(float x) {
    return fmaxf(x, 0.0f) + log1pf(expf(-fabsf(x)));
}
__device__ __forceinline__ float wred_max(float v) {
#pragma unroll
    for (int o = 16; o > 0; o >>= 1) v = fmaxf(v, __shfl_xor_sync(0xffffffffu, v, o));
    return v;
}
__device__ __forceinline__ float wred_sum(float v) {
#pragma unroll
    for (int o = 16; o > 0; o >>= 1) v += __shfl_xor_sync(0xffffffffu, v, o);
    return v;
}

// Fused: PPB (m,b)-pairs per 256-thread block.
// Warps [0, K*PPB): one expm each (spread across SMSPs).
// Warps [K*PPB, 8): stage seq rows into smem (overlapped with expm).
// Then all 8 warps stream the gather (smem-only reads, coalesced STG.128).
template <int K, int PPB>
__global__ void __launch_bounds__(256, 3)
fused_kernel(const int*   __restrict__ seq,    // (m,b,L)
             const int*   __restrict__ ridx,   // (m,b)
             const float* __restrict__ tauk,   // (m,num_rates)
             const float* __restrict__ exch,   // (m,K,20,20)
             const float* __restrict__ eq,     // (m,K,20)
             float*       __restrict__ out,    // (m,b,L,K,20)
             int mb, int b, int L, int nr)
{
    constexpr int EW = K * PPB;                  // expm warps (<= 4 for our configs)
    extern __shared__ float smem[];
    float* sW   = smem;                          // [EW][SS]: Q/E scratch, then P row-major
    int*   sseq = (int*)(smem + EW * SS);        // [PPB][L]

    const int tid  = threadIdx.x;
    const int wid  = tid >> 5;
    const int lane = tid & 31;

    if (wid < EW) {
        const int pair = wid / K;
        const int kk   = wid - pair * K;
        const int pb   = blockIdx.x * PPB + pair;     // flattened (m,b)
        if (pb < mb) {
            const int mi = pb / b;
            const float* Ek = exch + (size_t)(mi * K + kk) * SS;
            const float* ek = eq   + (size_t)(mi * K + kk) * S;
            float* Ws = sW + wid * SS;

            // ---- softmax p (via smem broadcast in this warp's slot) ----
            float x  = (lane < S) ? ek[lane] : -3.0e38f;
            float mx = wred_max(x);
            float ex = (lane < S) ? expf(x - mx) : 0.0f;
            float pl = ex / wred_sum(ex);
            if (lane < S) Ws[lane] = pl;
            __syncwarp();

            // ---- row `lane` of unnormalized Q ----
            float qrow[S];
            float diag = 0.0f;
            if (lane < S) {
#pragma unroll
                for (int j = 0; j < S; j++) {
                    float r = (j == lane) ? 0.0f
                            : softplusf(0.5f * (Ek[lane * S + j] + Ek[j * S + lane]));
                    float q = r * Ws[j];
                    qrow[j] = q;
                    diag += q;
                }
                qrow[lane] = -diag;
            }
            float mue = wred_sum((lane < S) ? pl * diag : 0.0f);
            const float inv = 1.0f / fmaxf(mue, 1e-16f);
            __syncwarp();   // all lanes done reading p
            if (lane < S) {
#pragma unroll
                for (int j = 0; j < S; j++) Ws[j * S + lane] = qrow[j] * inv;  // col-major Q
            }
            const float an = wred_max((lane < S) ? 2.0f * diag * inv : 0.0f);

            // ---- tau + scaling (theta = 1.0) ----
            const float tau = softplusf(tauk[mi * nr + ridx[pb]]);
            float nrm = tau * an;
            int sc = 0;
            while (nrm > 1.0f && sc < 40) { nrm *= 0.5f; sc++; }
            const float factor = ldexpf(tau, -sc);
            __syncwarp();   // Q visible

            const float4* W4  = reinterpret_cast<const float4*>(Ws);
            const int     col = (lane < S) ? lane : 0;

            // ---- Horner Taylor, degree J: A=I+(f/J)Q; A <- I+(f/j)QA ----
            const int J = 11;
            float a[S];
#pragma unroll
            for (int i = 0; i < S; i++)
                a[i] = (factor / (float)J) * Ws[col * S + i] + ((i == lane) ? 1.0f : 0.0f);

#pragma unroll 1
            for (int j = J - 1; j >= 1; j--) {
                const float coef = factor / (float)j;
                float c[S];
#pragma unroll
                for (int i = 0; i < S; i++) c[i] = 0.0f;
#pragma unroll
                for (int t = 0; t < S; t++) {
                    const float av = a[t];
#pragma unroll
                    for (int q = 0; q < 5; q++) {
                        float4 v = W4[t * 5 + q];
                        c[4*q+0] = fmaf(v.x, av, c[4*q+0]);
                        c[4*q+1] = fmaf(v.y, av, c[4*q+1]);
                        c[4*q+2] = fmaf(v.z, av, c[4*q+2]);
                        c[4*q+3] = fmaf(v.w, av, c[4*q+3]);
                    }
                }
#pragma unroll
                for (int i = 0; i < S; i++) a[i] = coef * c[i] + ((i == lane) ? 1.0f : 0.0f);
            }

            // ---- squarings ----
#pragma unroll 1
            for (int r = 0; r < sc; r++) {
                __syncwarp();
                if (lane < S) {
#pragma unroll
                    for (int i = 0; i < S; i++) Ws[lane * S + i] = a[i];  // E col-major
                }
                __syncwarp();
                float c[S];
#pragma unroll
                for (int i = 0; i < S; i++) c[i] = 0.0f;
#pragma unroll
                for (int t = 0; t < S; t++) {
                    const float av = a[t];
#pragma unroll
                    for (int q = 0; q < 5; q++) {
                        float4 v = W4[t * 5 + q];
                        c[4*q+0] = fmaf(v.x, av, c[4*q+0]);
                        c[4*q+1] = fmaf(v.y, av, c[4*q+1]);
                        c[4*q+2] = fmaf(v.z, av, c[4*q+2]);
                        c[4*q+3] = fmaf(v.w, av, c[4*q+3]);
                    }
                }
#pragma unroll
                for (int i = 0; i < S; i++) a[i] = c[i];
            }

            // ---- final P row-major into same slot ----
            __syncwarp();
            if (lane < S) {
#pragma unroll
                for (int i = 0; i < S; i++) Ws[i * S + col] = a[i];
            }
        }
    } else {
        // ---- stage seq rows (overlapped with expm) ----
        const int stid = (tid - EW * 32);
        const int nst  = (8 - EW) * 32;
        const int tot  = PPB * L;
        for (int i = stid; i < tot; i += nst) {
            const int p  = i / L;
            const int o  = i - p * L;
            const int pb = blockIdx.x * PPB + p;
            sseq[i] = (pb < mb) ? __ldg(seq + (size_t)pb * L + o) : 0;
        }
    }
    __syncthreads();

    // ---------------- gather: out[pb,l,k,:] = P[k][seq[l],:] ----------------
    const int nf4 = L * K * 5;
#pragma unroll 1
    for (int p = 0; p < PPB; p++) {
        const int pb = blockIdx.x * PPB + p;
        if (pb >= mb) break;
        float4*       out4 = reinterpret_cast<float4*>(out) + (size_t)pb * nf4;
        const float4* P4   = reinterpret_cast<const float4*>(sW + p * K * SS);
        const int*    sq   = sseq + p * L;

#pragma unroll 4
        for (int g = tid; g < nf4; g += 256) {
            const int l  = g / (K * 5);
            const int j  = g - l * (K * 5);
            const int kq = j / 5;
            const int s4 = j - kq * 5;
            __stcs(&out4[g], P4[kq * 100 + sq[l] * 5 + s4]);
        }
    }
}

template <int K, int PPB>
static void launch(const int* seq, const int* ridx, const float* tauk,
                   const float* exch, const float* eq, float* out,
                   int mb, int b, int L, int nr)
{
    const int grid = (mb + PPB - 1) / PPB;
    const int smem = K * PPB * SS * (int)sizeof(float) + PPB * L * (int)sizeof(int);
    fused_kernel<K, PPB><<<grid, 256, smem>>>(seq, ridx, tauk, exch, eq, out, mb, b, L, nr);
}

extern "C" void kernel_launch(void* const* d_in, const int* in_sizes, int n_in,
                              void* d_out, int out_size)
{
    const int*   seq  = (const int*)  d_in[0];
    const int*   ridx = (const int*)  d_in[1];
    const float* tauk = (const float*)d_in[2];
    const float* exch = (const float*)d_in[3];
    const float* eq   = (const float*)d_in[4];
    float*       out  = (float*)d_out;

    const int n_seq = in_sizes[0];
    const int n_ri  = in_sizes[1];
    const int n_tau = in_sizes[2];
    const int n_eq  = in_sizes[4];

    const int mk = n_eq / S;
    const int k  = out_size / (n_seq * S);
    const int m  = mk / k;
    const int b  = n_ri / m;
    const int L  = n_seq / n_ri;
    const int nr = n_tau / m;
    const int mb = m * b;

    switch (k) {
        case 1: launch<1, 2>(seq, ridx, tauk, exch, eq, out, mb, b, L, nr); break;
        case 2: launch<2, 2>(seq, ridx, tauk, exch, eq, out, mb, b, L, nr); break;
        case 3: launch<3, 1>(seq, ridx, tauk, exch, eq, out, mb, b, L, nr); break;
        case 4: launch<4, 1>(seq, ridx, tauk, exch, eq, out, mb, b, L, nr); break;
        default: break;
    }
}

// round 5
// speedup vs baseline: 4.1841x; 3.5745x over previous
#include <cuda_runtime.h>
#include <math.h>

#define S   20
#define SS  400
#define J   15          // number of precomputed powers / Taylor degree
#define THETA 2.0f      // scale so ||f*Q||_inf <= THETA

// ---- device scratch (allocation-free rule) ----
__device__ float g_Qpow[64 * J * SS];   // per (m,k): powers Q^1..Q^J, row-major
__device__ float g_an[64];              // per (m,k): ||Q||_inf

__device__ __forceinline__ float softplusf(float x) {
    return fmaxf(x, 0.0f) + log1pf(expf(-fabsf(x)));
}
__device__ __forceinline__ float wred_max(float v) {
#pragma unroll
    for (int o = 16; o > 0; o >>= 1) v = fmaxf(v, __shfl_xor_sync(0xffffffffu, v, o));
    return v;
}
__device__ __forceinline__ float wred_sum(float v) {
#pragma unroll
    for (int o = 16; o > 0; o >>= 1) v += __shfl_xor_sync(0xffffffffu, v, o);
    return v;
}

// c[i] = sum_t M[t*20+i] * a[t]   (M col-major, f4-aligned)
__device__ __forceinline__ void matvec_cols(const float* __restrict__ M,
                                            const float* __restrict__ a,
                                            float* __restrict__ c) {
#pragma unroll
    for (int i = 0; i < S; i++) c[i] = 0.0f;
    const float4* M4 = reinterpret_cast<const float4*>(M);
#pragma unroll
    for (int t = 0; t < S; t++) {
        const float av = a[t];
#pragma unroll
        for (int q = 0; q < 5; q++) {
            float4 v = M4[t * 5 + q];
            c[4*q+0] = fmaf(v.x, av, c[4*q+0]);
            c[4*q+1] = fmaf(v.y, av, c[4*q+1]);
            c[4*q+2] = fmaf(v.z, av, c[4*q+2]);
            c[4*q+3] = fmaf(v.w, av, c[4*q+3]);
        }
    }
}

// ---------------- setup: one block per (m,k) matrix; warp w computes Q^{w+1} ----------------
__global__ void __launch_bounds__(32 * J)
setup_kernel(const float* __restrict__ exch,   // (mk,20,20)
             const float* __restrict__ eq)     // (mk,20)
{
    __shared__ __align__(16) float sQ[SS];          // Q col-major
    __shared__ __align__(16) float slot[J][SS];     // per-warp scratch (col-major)
    __shared__ float sp[S];

    const int mat  = blockIdx.x;
    const int wid  = threadIdx.x >> 5;
    const int lane = threadIdx.x & 31;

    if (wid == 0) {
        const float* Ek = exch + (size_t)mat * SS;
        const float* ek = eq   + (size_t)mat * S;
        // softmax p
        float x  = (lane < S) ? ek[lane] : -3.0e38f;
        float mx = wred_max(x);
        float ex = (lane < S) ? expf(x - mx) : 0.0f;
        float pl = ex / wred_sum(ex);
        if (lane < S) sp[lane] = pl;
        __syncwarp();
        // row `lane` of unnormalized Q
        float qrow[S];
        float diag = 0.0f;
        if (lane < S) {
#pragma unroll
            for (int j = 0; j < S; j++) {
                float r = (j == lane) ? 0.0f
                        : softplusf(0.5f * (Ek[lane * S + j] + Ek[j * S + lane]));
                float q = r * sp[j];
                qrow[j] = q;
                diag += q;
            }
            qrow[lane] = -diag;
        }
        float mue = wred_sum((lane < S) ? pl * diag : 0.0f);
        const float inv = 1.0f / fmaxf(mue, 1e-16f);
        if (lane < S) {
#pragma unroll
            for (int j = 0; j < S; j++) sQ[j * S + lane] = qrow[j] * inv;  // col-major
        }
        const float an = wred_max((lane < S) ? 2.0f * diag * inv : 0.0f);
        if (lane == 0) g_an[mat] = an;
    }
    __syncthreads();

    // binary exponentiation: this warp computes Q^p, p = wid+1
    const int p   = wid + 1;
    const int col = (lane < S) ? lane : 0;
    float a[S], c[S];
#pragma unroll
    for (int i = 0; i < S; i++) a[i] = sQ[col * S + i];

    const int hb = 31 - __clz(p);
    for (int bit = hb - 1; bit >= 0; bit--) {
        // square: stash current result col-major in own slot
        __syncwarp();
        if (lane < S) {
#pragma unroll
            for (int i = 0; i < S; i++) slot[wid][col * S + i] = a[i];
        }
        __syncwarp();
        matvec_cols(&slot[wid][0], a, c);
#pragma unroll
        for (int i = 0; i < S; i++) a[i] = c[i];
        if ((p >> bit) & 1) {
            matvec_cols(sQ, a, c);
#pragma unroll
            for (int i = 0; i < S; i++) a[i] = c[i];
        }
    }

    // store ROW-major: element [i][col] at i*20+col
    if (lane < S) {
        float* dst = g_Qpow + ((size_t)mat * J + (p - 1)) * SS;
#pragma unroll
        for (int i = 0; i < S; i++) dst[i * S + col] = a[i];
    }
}

// ---------------- main: one block per (m,b); warps [0,K) expm-lincomb, rest stage seq ----------------
template <int K>
__global__ void __launch_bounds__(256, 4)
main_kernel(const int*   __restrict__ seq,    // (m,b,L)
            const int*   __restrict__ ridx,   // (m,b)
            const float* __restrict__ tauk,   // (m,num_rates)
            float*       __restrict__ out,    // (m,b,L,K,20)
            int b, int L, int nr)
{
    extern __shared__ float smem[];
    float* sP   = smem;                    // [K][SS] row-major P
    int*   sseq = (int*)(smem + K * SS);   // [L]

    const int pb   = blockIdx.x;           // flattened (m,b)
    const int tid  = threadIdx.x;
    const int wid  = tid >> 5;
    const int lane = tid & 31;

    if (wid < K) {
        const int mi  = pb / b;
        const int mat = mi * K + wid;
        float* Ps = sP + wid * SS;

        const float tau = softplusf(tauk[mi * nr + ridx[pb]]);
        const float an  = g_an[mat];
        float f = tau;
        int   s = 0;
        while (f * an > THETA && s < 40) { f *= 0.5f; s++; }

        const float4* T4 = reinterpret_cast<const float4*>(g_Qpow + (size_t)mat * J * SS);

        // lane owns f4 chunks n = lane, lane+32, lane+64 (+96 for lanes<4)
        float4 acc[4];
#pragma unroll
        for (int u = 0; u < 4; u++) {
            const int n = lane + 32 * u;
            float4 id = make_float4(0.f, 0.f, 0.f, 0.f);
            if (n < 100) {
                const int e = 4 * n;
                if ((e+0) / S == (e+0) % S) id.x = 1.0f;
                if ((e+1) / S == (e+1) % S) id.y = 1.0f;
                if ((e+2) / S == (e+2) % S) id.z = 1.0f;
                if ((e+3) / S == (e+3) % S) id.w = 1.0f;
            }
            acc[u] = id;
        }

        float coef = 1.0f;
#pragma unroll 1
        for (int j = 0; j < J; j++) {
            coef *= f / (float)(j + 1);
#pragma unroll
            for (int u = 0; u < 3; u++) {
                float4 v = T4[j * 100 + lane + 32 * u];
                acc[u].x = fmaf(coef, v.x, acc[u].x);
                acc[u].y = fmaf(coef, v.y, acc[u].y);
                acc[u].z = fmaf(coef, v.z, acc[u].z);
                acc[u].w = fmaf(coef, v.w, acc[u].w);
            }
            if (lane < 4) {
                float4 v = T4[j * 100 + lane + 96];
                acc[3].x = fmaf(coef, v.x, acc[3].x);
                acc[3].y = fmaf(coef, v.y, acc[3].y);
                acc[3].z = fmaf(coef, v.z, acc[3].z);
                acc[3].w = fmaf(coef, v.w, acc[3].w);
            }
        }

        // write E row-major to smem
        float4* Ps4 = reinterpret_cast<float4*>(Ps);
        Ps4[lane]      = acc[0];
        Ps4[lane + 32] = acc[1];
        Ps4[lane + 64] = acc[2];
        if (lane < 4) Ps4[lane + 96] = acc[3];

        if (s > 0) {  // cold path: square s times (col-in-registers, scalar broadcasts)
            __syncwarp();
            const int col = (lane < S) ? lane : 0;
            float a[S];
#pragma unroll
            for (int i = 0; i < S; i++) a[i] = Ps[i * S + col];
#pragma unroll 1
            for (int r = 0; r < s; r++) {
                float c[S];
#pragma unroll
                for (int i = 0; i < S; i++) c[i] = 0.0f;
#pragma unroll
                for (int t = 0; t < S; t++) {
                    const float av = a[t];
#pragma unroll
                    for (int i = 0; i < S; i++) c[i] = fmaf(Ps[i * S + t], av, c[i]);
                }
                __syncwarp();
                if (lane < S) {
#pragma unroll
                    for (int i = 0; i < S; i++) Ps[i * S + col] = c[i];
                }
                __syncwarp();
#pragma unroll
                for (int i = 0; i < S; i++) a[i] = c[i];
            }
        }
    } else {
        // stage sequence row (overlapped with expm)
        const int stid = tid - K * 32;
        const int nst  = 256 - K * 32;
        for (int i = stid; i < L; i += nst) sseq[i] = __ldg(seq + (size_t)pb * L + i);
    }
    __syncthreads();

    // ---------------- gather: out[pb,l,k,:] = P[k][seq[l],:] ----------------
    const int nf4 = L * K * 5;
    float4*       out4 = reinterpret_cast<float4*>(out) + (size_t)pb * nf4;
    const float4* P4   = reinterpret_cast<const float4*>(sP);

#pragma unroll 4
    for (int g = tid; g < nf4; g += 256) {
        const int l  = g / (K * 5);
        const int j  = g - l * (K * 5);
        const int kq = j / 5;
        const int s4 = j - kq * 5;
        __stcs(&out4[g], P4[kq * 100 + sseq[l] * 5 + s4]);
    }
}

extern "C" void kernel_launch(void* const* d_in, const int* in_sizes, int n_in,
                              void* d_out, int out_size)
{
    const int*   seq  = (const int*)  d_in[0];
    const int*   ridx = (const int*)  d_in[1];
    const float* tauk = (const float*)d_in[2];
    const float* exch = (const float*)d_in[3];
    const float* eq   = (const float*)d_in[4];
    float*       out  = (float*)d_out;

    const int n_seq = in_sizes[0];
    const int n_ri  = in_sizes[1];
    const int n_tau = in_sizes[2];
    const int n_eq  = in_sizes[4];

    const int mk = n_eq / S;
    const int k  = out_size / (n_seq * S);
    const int m  = mk / k;
    const int b  = n_ri / m;
    const int L  = n_seq / n_ri;
    const int nr = n_tau / m;
    const int mb = m * b;

    setup_kernel<<<mk, 32 * J>>>(exch, eq);

    const int smem = k * SS * (int)sizeof(float) + L * (int)sizeof(int);
    switch (k) {
        case 1: main_kernel<1><<<mb, 256, smem>>>(seq, ridx, tauk, out, b, L, nr); break;
        case 2: main_kernel<2><<<mb, 256, smem>>>(seq, ridx, tauk, out, b, L, nr); break;
        case 3: main_kernel<3><<<mb, 256, smem>>>(seq, ridx, tauk, out, b, L, nr); break;
        case 4: main_kernel<4><<<mb, 256, smem>>>(seq, ridx, tauk, out, b, L, nr); break;
        default: break;
    }
}